// round 5
// baseline (speedup 1.0000x reference)
#include <cuda_runtime.h>
#include <cuda_bf16.h>
#include <cstddef>

#define BATCH 16
#define CH    512
#define S     128

// Per-batch branch accumulators + completion counters.
// Zero-initialized at load; the epilogue (last block per batch) re-zeroes
// them, so they are always zero on entry to kernel_launch.
__device__ float g_ww_raw[BATCH * S];
__device__ float g_hw_raw[BATCH * S];
__device__ int   g_cnt[BATCH];

// ---------------------------------------------------------------------------
// K1: one block per (b, h) row. Streams x[b, :, h, :] (256 KB), computes the
// 2-channel 1x1-conv row, accumulates branch contributions atomically.
// The LAST block to finish for a batch runs the fused epilogue:
// linear + sigmoid + outer product for that batch.
// ---------------------------------------------------------------------------
__global__ __launch_bounds__(128, 16) void swa_k1(
    const float4* __restrict__ x4,
    const float*  __restrict__ wconv,   // [2,512]
    const float*  __restrict__ www,     // [1,2,128,5]
    const float*  __restrict__ whw,     // [1,2,5,128]
    const float*  __restrict__ wwlw,    // [128,128]
    const float*  __restrict__ wwlb,    // [128]
    const float*  __restrict__ hwlw,    // [128,128]
    const float*  __restrict__ hwlb,    // [128]
    float*        __restrict__ out)     // [B,128,128]
{
    __shared__ float s_wc[2][CH];          // 4 KB
    __shared__ float s_red[4][2][S];       // 4 KB
    __shared__ float s_x2[2][S];           // 1 KB (reused as raw vecs in epi)
    __shared__ float s_sig[2][S];          // 1 KB (epilogue sigmoids)
    __shared__ float s_hwred[4][5];
    __shared__ int   s_last;

    const int h = blockIdx.x;
    const int b = blockIdx.y;
    const int t = threadIdx.x;
    const int wp = t >> 5;
    const int ln = t & 31;

    // load 1x1-conv weights [2,512] into shared
    #pragma unroll
    for (int i = t; i < 2 * CH; i += 128) s_wc[i >> 9][i & 511] = wconv[i];
    __syncthreads();

    // ---- streaming mainloop: 4 channel groups x 32 float4 positions ----
    const int w4 = ln;          // float4 position within row
    const int cg = wp;          // channel group 0..3

    size_t base4 = ((size_t)(b * CH + cg * 128) * S + (size_t)h) * (S / 4) + (size_t)w4;

    float a00 = 0.f, a01 = 0.f, a02 = 0.f, a03 = 0.f;
    float a10 = 0.f, a11 = 0.f, a12 = 0.f, a13 = 0.f;

    #pragma unroll 8
    for (int c = 0; c < 128; c++) {
        float4 v = __ldg(&x4[base4 + (size_t)c * (S * S / 4)]);
        float w0 = s_wc[0][cg * 128 + c];
        float w1 = s_wc[1][cg * 128 + c];
        a00 += v.x * w0; a01 += v.y * w0; a02 += v.z * w0; a03 += v.w * w0;
        a10 += v.x * w1; a11 += v.y * w1; a12 += v.z * w1; a13 += v.w * w1;
    }

    s_red[cg][0][w4 * 4 + 0] = a00;
    s_red[cg][0][w4 * 4 + 1] = a01;
    s_red[cg][0][w4 * 4 + 2] = a02;
    s_red[cg][0][w4 * 4 + 3] = a03;
    s_red[cg][1][w4 * 4 + 0] = a10;
    s_red[cg][1][w4 * 4 + 1] = a11;
    s_red[cg][1][w4 * 4 + 2] = a12;
    s_red[cg][1][w4 * 4 + 3] = a13;
    __syncthreads();

    {
        float s0 = 0.f, s1 = 0.f;
        #pragma unroll
        for (int g = 0; g < 4; g++) { s0 += s_red[g][0][t]; s1 += s_red[g][1][t]; }
        s_x2[0][t] = s0;
        s_x2[1][t] = s1;
    }
    __syncthreads();

    // --- hw branch: 5 dot products of the row with w_hw[o][kh][:] ---
    {
        const float x20 = s_x2[0][t];
        const float x21 = s_x2[1][t];
        float p[5];
        #pragma unroll
        for (int kh = 0; kh < 5; kh++)
            p[kh] = x20 * __ldg(&whw[kh * S + t]) + x21 * __ldg(&whw[(5 + kh) * S + t]);
        #pragma unroll
        for (int off = 16; off > 0; off >>= 1) {
            #pragma unroll
            for (int kh = 0; kh < 5; kh++)
                p[kh] += __shfl_down_sync(0xffffffffu, p[kh], off);
        }
        if (ln == 0) {
            #pragma unroll
            for (int kh = 0; kh < 5; kh++) s_hwred[wp][kh] = p[kh];
        }
    }

    // --- ww branch: 5-tap correlation along w, atomically accumulated ---
    {
        float acc = 0.f;
        #pragma unroll
        for (int kw = 0; kw < 5; kw++) {
            int wi = t - 2 + kw;
            if (wi >= 0 && wi < S)
                acc += s_x2[0][wi] * __ldg(&www[h * 5 + kw])
                     + s_x2[1][wi] * __ldg(&www[(S + h) * 5 + kw]);
        }
        atomicAdd(&g_ww_raw[b * S + t], acc);
    }
    __syncthreads();

    if (t < 5) {
        float v = s_hwred[0][t] + s_hwred[1][t] + s_hwred[2][t] + s_hwred[3][t];
        int hp = h + 2 - t;
        if (hp >= 0 && hp < S)
            atomicAdd(&g_hw_raw[b * S + hp], v);
    }

    // ---- last-block election ----
    __threadfence();
    if (t == 0)
        s_last = (atomicAdd(&g_cnt[b], 1) == S - 1) ? 1 : 0;
    __syncthreads();
    if (!s_last) return;

    // =================== fused epilogue (one block per batch) ==============
    // Consume + re-zero the raw vectors (bypass L1 on read).
    {
        float vw = __ldcg(&g_ww_raw[b * S + t]);
        float vh = __ldcg(&g_hw_raw[b * S + t]);
        g_ww_raw[b * S + t] = 0.f;
        g_hw_raw[b * S + t] = 0.f;
        s_x2[0][t] = vw;       // reuse s_x2 as raw-vector storage
        s_x2[1][t] = vh;
        if (t == 0) g_cnt[b] = 0;
    }
    __syncthreads();

    // Linear + sigmoid, both branches. Warp wp handles rows [wp*32, +32).
    // 4-row interleaved butterfly shuffles to pipeline SHFL latency.
    {
        const int rowbase = wp * 32;
        #pragma unroll
        for (int which = 0; which < 2; which++) {
            const float* W   = which ? hwlw : wwlw;
            const float* vec = s_x2[which];
            float v0 = vec[ln], v1 = vec[ln + 32], v2 = vec[ln + 64], v3 = vec[ln + 96];

            float myrow = 0.f;
            #pragma unroll
            for (int r0 = 0; r0 < 32; r0 += 4) {
                float p[4];
                #pragma unroll
                for (int k = 0; k < 4; k++) {
                    const float* Wr = W + (rowbase + r0 + k) * S;
                    p[k] = Wr[ln] * v0 + Wr[ln + 32] * v1 + Wr[ln + 64] * v2 + Wr[ln + 96] * v3;
                }
                #pragma unroll
                for (int off = 16; off > 0; off >>= 1) {
                    #pragma unroll
                    for (int k = 0; k < 4; k++)
                        p[k] += __shfl_xor_sync(0xffffffffu, p[k], off);
                }
                #pragma unroll
                for (int k = 0; k < 4; k++)
                    if (ln == r0 + k) myrow = p[k];
            }

            const int i = rowbase + ln;
            float acc = myrow + (which ? hwlb[i] : wwlb[i]);
            s_sig[which][i] = 1.f / (1.f + expf(-acc));
        }
    }
    __syncthreads();

    // Outer product: out[b][hh][w] = hw_sig[hh] * ww_sig[w]
    float4* o4 = (float4*)(out + (size_t)b * S * S);
    const float4* ww4 = (const float4*)&s_sig[0][0];
    #pragma unroll 8
    for (int i = t; i < S * S / 4; i += 128) {
        int hh = i >> 5;
        int wq = i & 31;
        float hv = s_sig[1][hh];
        float4 wv = ww4[wq];
        o4[i] = make_float4(hv * wv.x, hv * wv.y, hv * wv.z, hv * wv.w);
    }
}

extern "C" void kernel_launch(void* const* d_in, const int* in_sizes, int n_in,
                              void* d_out, int out_size)
{
    const float* x     = (const float*)d_in[0];
    const float* wconv = (const float*)d_in[1];
    const float* www   = (const float*)d_in[2];
    const float* whw   = (const float*)d_in[3];
    const float* wwlw  = (const float*)d_in[4];
    const float* wwlb  = (const float*)d_in[5];
    const float* hwlw  = (const float*)d_in[6];
    const float* hwlb  = (const float*)d_in[7];
    float* out = (float*)d_out;

    dim3 g1(S, BATCH);
    swa_k1<<<g1, 128>>>((const float4*)x, wconv, www, whw,
                        wwlw, wwlb, hwlw, hwlb, out);
}